// round 16
// baseline (speedup 1.0000x reference)
#include <cuda_runtime.h>
#include <cuda_fp16.h>
#include <mma.h>
#include <cstdint>

using namespace nvcuda;

#define N_NODES 2048
#define F_DIM   128
#define UNITS   128
#define FE_DIM  16
#define DEG     64

#define GM_M    32                  // nodes per gemm block
#define GM_GRID ((N_NODES / GM_M) * 2)   // 64 groups x 2 sides = 128 blocks

__device__ __half g_hr[N_NODES * UNITS];
__device__ float  g_al[N_NODES];
__device__ float  g_ar[N_NODES];

__device__ __forceinline__ float lrelu(float x) {
    return x > 0.0f ? x : 0.2f * x;
}

// smem plan (dynamic, 57344B):
//   s_a: GM_M x 128 half   (8192B)
//   s_w: 128 x 128 half    (32768B)
//   s_c: GM_M x 128 float  (16384B)
#define SMEM_A_OFF 0
#define SMEM_W_OFF 8192
#define SMEM_C_OFF (8192 + 32768)
#define GEMM_SMEM  (8192 + 32768 + 16384)

// Kernel 1: wmma fp16 GEMM. 128 blocks x 256 threads.
//   block b: side = b>>6 (0=L,1=R), nodes [n0, n0+32).
//   Loads ns tile + FULL W into smem as fp16, 8 warps each compute a
//   16x32 output strip via m16n16k16 HMMA with fp32 accumulators.
__global__ __launch_bounds__(256)
void gemm_kernel(const float* __restrict__ ns,
                 const float* __restrict__ Wl,
                 const float* __restrict__ Wr,
                 const float* __restrict__ W_attn) {
    extern __shared__ char smem[];
    __half* s_a = reinterpret_cast<__half*>(smem + SMEM_A_OFF);
    __half* s_w = reinterpret_cast<__half*>(smem + SMEM_W_OFF);
    float*  s_c = reinterpret_cast<float*>(smem + SMEM_C_OFF);

    const int b    = blockIdx.x;
    const int side = b >> 6;                 // 0 = L, 1 = R
    const int n0   = (b & 63) * GM_M;
    const int t    = threadIdx.x;
    const int wid  = t >> 5, lane = t & 31;

    const float* __restrict__ W = side ? Wr : Wl;

    // load + convert ns tile: 32x128 fp32 -> fp16 (2048 float2)
    {
        const float2* src = reinterpret_cast<const float2*>(ns + n0 * F_DIM);
        __half2* dst = reinterpret_cast<__half2*>(s_a);
        #pragma unroll
        for (int i = t; i < GM_M * F_DIM / 2; i += 256)
            dst[i] = __float22half2_rn(src[i]);
    }
    // load + convert full W: 128x128 fp32 -> fp16 (8192 float2)
    {
        const float2* src = reinterpret_cast<const float2*>(W);
        __half2* dst = reinterpret_cast<__half2*>(s_w);
        #pragma unroll
        for (int i = t; i < F_DIM * UNITS / 2; i += 256)
            dst[i] = __float22half2_rn(src[i]);
    }
    __syncthreads();

    // warp wid: rows [rowb, rowb+16), cols [colb, colb+32)
    const int rowb = (wid >> 2) * 16;
    const int colb = (wid & 3) * 32;

    wmma::fragment<wmma::accumulator, 16, 16, 16, float> c0, c1;
    wmma::fill_fragment(c0, 0.0f);
    wmma::fill_fragment(c1, 0.0f);

    #pragma unroll
    for (int kk = 0; kk < F_DIM; kk += 16) {
        wmma::fragment<wmma::matrix_a, 16, 16, 16, __half, wmma::row_major> a;
        wmma::fragment<wmma::matrix_b, 16, 16, 16, __half, wmma::row_major> b0, b1;
        wmma::load_matrix_sync(a, s_a + rowb * F_DIM + kk, F_DIM);
        wmma::load_matrix_sync(b0, s_w + kk * UNITS + colb, UNITS);
        wmma::load_matrix_sync(b1, s_w + kk * UNITS + colb + 16, UNITS);
        wmma::mma_sync(c0, a, b0, c0);
        wmma::mma_sync(c1, a, b1, c1);
    }

    wmma::store_matrix_sync(s_c + rowb * UNITS + colb, c0, UNITS,
                            wmma::mem_row_major);
    wmma::store_matrix_sync(s_c + rowb * UNITS + colb + 16, c1, UNITS,
                            wmma::mem_row_major);
    __syncthreads();

    // epilogue 1: hr store (side R only), fp16, coalesced
    if (side) {
        #pragma unroll
        for (int i = t; i < GM_M * UNITS; i += 256)
            g_hr[n0 * UNITS + i] = __float2half_rn(s_c[i]);
    }

    // epilogue 2: per-node scalar  sum_col lrelu(c)*wa  (warp wid -> 4 nodes)
    #pragma unroll
    for (int j = 0; j < 4; j++) {
        const int node = wid * 4 + j;
        float p = 0.0f;
        #pragma unroll
        for (int c = lane; c < UNITS; c += 32)
            p += lrelu(s_c[node * UNITS + c]) * W_attn[side * UNITS + c];
        #pragma unroll
        for (int o = 16; o > 0; o >>= 1)
            p += __shfl_down_sync(0xffffffffu, p, o);
        if (lane == 0) {
            float* dstv = side ? g_ar : g_al;
            dstv[n0 + node] = p;
        }
    }
}

// Kernel 2: R13/R14 attn (proven 10.8us): 1 node/block, 128 threads;
// all-thread gather (2 threads/edge, 32B each), fp16 hr aggregation.
__global__ __launch_bounds__(128)
void attn_kernel(const int* __restrict__ edges,
                 const float* __restrict__ ef,
                 const float* __restrict__ W_edge,
                 const float* __restrict__ W_attn,
                 float* __restrict__ out) {
    const int n = blockIdx.x;
    const int t = threadIdx.x;
    const int w = t >> 5, lane = t & 31;

    __shared__ float s_wev[FE_DIM];
    __shared__ float s_pd[2][DEG];
    __shared__ float s_score[DEG];
    __shared__ int   s_dst[DEG];
    __shared__ float s_acc[4][UNITS];
    __shared__ float s_part[2];
    __shared__ float s_inv;

    if (t < FE_DIM) {
        float s = 0.0f;
        #pragma unroll
        for (int j = 0; j < FE_DIM; j++)
            s += W_edge[t * FE_DIM + j] * W_attn[2 * UNITS + j];
        s_wev[t] = s;
    }
    if (t < DEG)
        s_dst[t] = reinterpret_cast<const int2*>(edges)[n * DEG + t].y;
    __syncthreads();

    // gather: all 128 threads; thread = (edge er, half hf); 32B per thread.
    {
        const int er = t & 63;
        const int hf = t >> 6;
        const int dst = s_dst[er];
        const float4* p = reinterpret_cast<const float4*>(
            ef + ((size_t)n * N_NODES + (size_t)dst) * FE_DIM) + hf * 2;
        const float4 v0 = p[0];
        const float4 v1 = p[1];
        const float* wv = &s_wev[hf * 8];
        float d = 0.0f;
        d = fmaf(v0.x, wv[0], d);
        d = fmaf(v0.y, wv[1], d);
        d = fmaf(v0.z, wv[2], d);
        d = fmaf(v0.w, wv[3], d);
        d = fmaf(v1.x, wv[4], d);
        d = fmaf(v1.y, wv[5], d);
        d = fmaf(v1.z, wv[6], d);
        d = fmaf(v1.w, wv[7], d);
        s_pd[hf][er] = d;
    }
    __syncthreads();

    if (t < DEG) {
        const int dst = s_dst[t];
        float s = g_al[n] + g_ar[dst] + s_pd[0][t] + s_pd[1][t];
        s = fminf(2.0f, fmaxf(-2.0f, s));
        const float sc = __expf(s);
        s_score[t] = sc;

        float v = sc;
        #pragma unroll
        for (int o = 16; o > 0; o >>= 1)
            v += __shfl_down_sync(0xffffffffu, v, o);
        if (lane == 0) s_part[t >> 5] = v;
    }
    __syncthreads();
    if (t == 0) s_inv = 1.0f / (s_part[0] + s_part[1]);

    const int ebase = w * 16;
    const int sub   = lane >> 4;
    const int c0    = (lane & 15) * 8;

    float acc[8];
    #pragma unroll
    for (int k = 0; k < 8; k++) acc[k] = 0.0f;

    #pragma unroll
    for (int i = 0; i < 8; i++) {
        const int e = ebase + 2 * i + sub;
        const float sc = s_score[e];
        const int4 hv = *reinterpret_cast<const int4*>(
            g_hr + s_dst[e] * UNITS + c0);
        const __half2* hp = reinterpret_cast<const __half2*>(&hv);
        #pragma unroll
        for (int k = 0; k < 4; k++) {
            const float2 f = __half22float2(hp[k]);
            acc[2 * k]     = fmaf(sc, f.x, acc[2 * k]);
            acc[2 * k + 1] = fmaf(sc, f.y, acc[2 * k + 1]);
        }
    }
    #pragma unroll
    for (int k = 0; k < 8; k++)
        acc[k] += __shfl_down_sync(0xffffffffu, acc[k], 16);

    if (lane < 16) {
        *reinterpret_cast<float4*>(&s_acc[w][c0]) =
            make_float4(acc[0], acc[1], acc[2], acc[3]);
        *reinterpret_cast<float4*>(&s_acc[w][c0 + 4]) =
            make_float4(acc[4], acc[5], acc[6], acc[7]);
    }
    __syncthreads();

    out[n * UNITS + t] =
        (s_acc[0][t] + s_acc[1][t] + s_acc[2][t] + s_acc[3][t]) * s_inv;
}

extern "C" void kernel_launch(void* const* d_in, const int* in_sizes, int n_in,
                              void* d_out, int out_size) {
    const float* ns      = (const float*)d_in[0];
    const int*   edges   = (const int*)d_in[1];
    const float* ef      = (const float*)d_in[2];
    const float* W_left  = (const float*)d_in[3];
    const float* W_right = (const float*)d_in[4];
    const float* W_attn  = (const float*)d_in[5];
    const float* W_edge  = (const float*)d_in[6];
    float* out = (float*)d_out;

    // host attribute set (not a stream op; no device allocation)
    cudaFuncSetAttribute(gemm_kernel,
                         cudaFuncAttributeMaxDynamicSharedMemorySize, GEMM_SMEM);

    gemm_kernel<<<GM_GRID, 256, GEMM_SMEM>>>(ns, W_left, W_right, W_attn);
    attn_kernel<<<N_NODES, 128>>>(edges, ef, W_edge, W_attn, out);
}

// round 17
// speedup vs baseline: 1.2260x; 1.2260x over previous
#include <cuda_runtime.h>
#include <cuda_fp16.h>
#include <cstdint>

#define N_NODES 2048
#define F_DIM   128
#define UNITS   128
#define FE_DIM  16
#define DEG     64

__device__ __half g_hr[N_NODES * UNITS];   // fp16 hr
__device__ float  g_al[N_NODES];
__device__ float  g_ar[N_NODES];

__device__ __forceinline__ float lrelu(float x) {
    return x > 0.0f ? x : 0.2f * x;
}

__device__ __forceinline__ unsigned long long pack2(float lo, float hi) {
    unsigned long long r;
    asm("mov.b64 %0, {%1, %2};" : "=l"(r) : "f"(lo), "f"(hi));
    return r;
}
__device__ __forceinline__ void unpack2(float& lo, float& hi, unsigned long long v) {
    asm("mov.b64 {%0, %1}, %2;" : "=f"(lo), "=f"(hi) : "l"(v));
}
__device__ __forceinline__ void fma2(unsigned long long& d,
                                     unsigned long long a,
                                     unsigned long long b) {
    asm("fma.rn.f32x2 %0, %1, %2, %3;" : "=l"(d) : "l"(a), "l"(b), "l"(d));
}

// Kernel 1: side-split GEMM — exact R8/R14 body (proven ~6.5us).
#define NPB   8
#define NSPAD 12
__global__ __launch_bounds__(128)
void gemm_kernel(const float* __restrict__ ns,
                 const float* __restrict__ Wl,
                 const float* __restrict__ Wr,
                 const float* __restrict__ W_attn) {
    const int b    = blockIdx.x;
    const int side = b >> 8;               // 0 = L, 1 = R
    const int t    = threadIdx.x;
    const int n0   = (b & 255) * NPB;

    __shared__ float s_ns[F_DIM][NSPAD];
    #pragma unroll
    for (int j = 0; j < NPB; j++)
        s_ns[t][j] = ns[(n0 + j) * F_DIM + t];
    __syncthreads();

    const float* __restrict__ W = side ? Wr : Wl;

    unsigned long long acc[4];
    #pragma unroll
    for (int j = 0; j < 4; j++) acc[j] = 0ull;

    #pragma unroll 8
    for (int k = 0; k < F_DIM; k++) {
        const float wv = W[k * UNITS + t];
        const unsigned long long wp = pack2(wv, wv);
        const ulonglong2* row = reinterpret_cast<const ulonglong2*>(&s_ns[k][0]);
        const ulonglong2 r0 = row[0];
        const ulonglong2 r1 = row[1];
        fma2(acc[0], r0.x, wp);
        fma2(acc[1], r0.y, wp);
        fma2(acc[2], r1.x, wp);
        fma2(acc[3], r1.y, wp);
    }

    float h[NPB];
    #pragma unroll
    for (int j = 0; j < 4; j++) unpack2(h[2 * j], h[2 * j + 1], acc[j]);

    if (side) {
        #pragma unroll
        for (int j = 0; j < NPB; j++)
            g_hr[(n0 + j) * UNITS + t] = __float2half_rn(h[j]);
    }

    const float wa = W_attn[side * UNITS + t];
    __shared__ float s_red[NPB][4];
    const int w = t >> 5, lane = t & 31;

    #pragma unroll
    for (int j = 0; j < NPB; j++) {
        float p = lrelu(h[j]) * wa;
        #pragma unroll
        for (int o = 16; o > 0; o >>= 1)
            p += __shfl_down_sync(0xffffffffu, p, o);
        if (lane == 0) s_red[j][w] = p;
    }
    __syncthreads();
    if (t < NPB) {
        float* dstv = side ? g_ar : g_al;
        dstv[n0 + t] = s_red[t][0] + s_red[t][1] + s_red[t][2] + s_red[t][3];
    }
}

// Kernel 2: pipelined attn. The 8 hr-row loads per thread (aggregation
// inputs, score-independent) are issued BEFORE the ef gather completes,
// overlapping the DRAM gather latency with the L2 hr-load latency.
__global__ __launch_bounds__(128)
void attn_kernel(const int* __restrict__ edges,
                 const float* __restrict__ ef,
                 const float* __restrict__ W_edge,
                 const float* __restrict__ W_attn,
                 float* __restrict__ out) {
    const int n = blockIdx.x;
    const int t = threadIdx.x;
    const int w = t >> 5, lane = t & 31;

    __shared__ float s_wev[FE_DIM];
    __shared__ float s_pd[2][DEG];
    __shared__ float s_score[DEG];
    __shared__ int   s_dst[DEG];
    __shared__ float s_acc[4][UNITS];
    __shared__ float s_part[2];
    __shared__ float s_inv;

    if (t < FE_DIM) {
        float s = 0.0f;
        #pragma unroll
        for (int j = 0; j < FE_DIM; j++)
            s += W_edge[t * FE_DIM + j] * W_attn[2 * UNITS + j];
        s_wev[t] = s;
    }
    if (t < DEG)
        s_dst[t] = reinterpret_cast<const int2*>(edges)[n * DEG + t].y;
    __syncthreads();

    // ---- issue ALL memory up front ----
    // (a) ef gather: 2 threads per edge, 32B each (DRAM, ~600cyc)
    const int er = t & 63;
    const int hf = t >> 6;
    const float4* p = reinterpret_cast<const float4*>(
        ef + ((size_t)n * N_NODES + (size_t)s_dst[er]) * FE_DIM) + hf * 2;
    const float4 v0 = p[0];
    const float4 v1 = p[1];

    // (b) hr aggregation rows: 8 independent int4 loads (L2, ~300cyc),
    //     held in registers until scores are ready.
    const int ebase = w * 16;
    const int sub   = lane >> 4;
    const int c0    = (lane & 15) * 8;
    int4 hv[8];
    #pragma unroll
    for (int i = 0; i < 8; i++) {
        const int e = ebase + 2 * i + sub;
        hv[i] = *reinterpret_cast<const int4*>(g_hr + s_dst[e] * UNITS + c0);
    }

    // partial dot from the ef halves
    {
        const float* wv = &s_wev[hf * 8];
        float d = 0.0f;
        d = fmaf(v0.x, wv[0], d);
        d = fmaf(v0.y, wv[1], d);
        d = fmaf(v0.z, wv[2], d);
        d = fmaf(v0.w, wv[3], d);
        d = fmaf(v1.x, wv[4], d);
        d = fmaf(v1.y, wv[5], d);
        d = fmaf(v1.z, wv[6], d);
        d = fmaf(v1.w, wv[7], d);
        s_pd[hf][er] = d;
    }
    __syncthreads();

    // scores + softmax denominator (threads 0..63)
    if (t < DEG) {
        const int dst = s_dst[t];
        float s = g_al[n] + g_ar[dst] + s_pd[0][t] + s_pd[1][t];
        s = fminf(2.0f, fmaxf(-2.0f, s));
        const float sc = __expf(s);
        s_score[t] = sc;

        float v = sc;
        #pragma unroll
        for (int o = 16; o > 0; o >>= 1)
            v += __shfl_down_sync(0xffffffffu, v, o);
        if (lane == 0) s_part[t >> 5] = v;
    }
    __syncthreads();
    if (t == 0) s_inv = 1.0f / (s_part[0] + s_part[1]);

    // aggregation FMAs on the pre-loaded hr rows
    float acc[8];
    #pragma unroll
    for (int k = 0; k < 8; k++) acc[k] = 0.0f;

    #pragma unroll
    for (int i = 0; i < 8; i++) {
        const float sc = s_score[ebase + 2 * i + sub];
        const __half2* hp = reinterpret_cast<const __half2*>(&hv[i]);
        #pragma unroll
        for (int k = 0; k < 4; k++) {
            const float2 f = __half22float2(hp[k]);
            acc[2 * k]     = fmaf(sc, f.x, acc[2 * k]);
            acc[2 * k + 1] = fmaf(sc, f.y, acc[2 * k + 1]);
        }
    }
    #pragma unroll
    for (int k = 0; k < 8; k++)
        acc[k] += __shfl_down_sync(0xffffffffu, acc[k], 16);

    if (lane < 16) {
        *reinterpret_cast<float4*>(&s_acc[w][c0]) =
            make_float4(acc[0], acc[1], acc[2], acc[3]);
        *reinterpret_cast<float4*>(&s_acc[w][c0 + 4]) =
            make_float4(acc[4], acc[5], acc[6], acc[7]);
    }
    __syncthreads();

    out[n * UNITS + t] =
        (s_acc[0][t] + s_acc[1][t] + s_acc[2][t] + s_acc[3][t]) * s_inv;
}

extern "C" void kernel_launch(void* const* d_in, const int* in_sizes, int n_in,
                              void* d_out, int out_size) {
    const float* ns      = (const float*)d_in[0];
    const int*   edges   = (const int*)d_in[1];
    const float* ef      = (const float*)d_in[2];
    const float* W_left  = (const float*)d_in[3];
    const float* W_right = (const float*)d_in[4];
    const float* W_attn  = (const float*)d_in[5];
    const float* W_edge  = (const float*)d_in[6];
    float* out = (float*)d_out;

    gemm_kernel<<<512, 128>>>(ns, W_left, W_right, W_attn);
    attn_kernel<<<N_NODES, 128>>>(edges, ef, W_edge, W_attn, out);
}